// round 11
// baseline (speedup 1.0000x reference)
#include <cuda_runtime.h>
#include <cstdint>

#define UNITS  512
#define NIN    256
#define NBATCH 512
#define JT 32          // j-columns per CTA
#define BT 16          // batches per CTA
#define NB 4           // batches per thread
#define NTHR 128
#define VSTR 20        // smem row stride (floats): float4-aligned, broadcast reads
#define PCH 16         // i's per cp.async-staged param chunk (8 KB)

// ---------------- device scratch (static, no runtime allocation) -------------
__device__ float4 RPd[UNITS*UNITS];   // recurrent params {s, c, Wh, WEh}
__device__ float4 SPd[NIN*UNITS];     // sensory params
__device__ float2 QP0[NBATCH*UNITS];  // partial (num,den), i-half 0
__device__ float2 QP1[NBATCH*UNITS];  // partial (num,den), i-half 1
__device__ float  NSd[NBATCH*UNITS];  // sensory numerator term [b][j]
__device__ float  DSd[NBATCH*UNITS];  // sensory denominator term [b][j]
__device__ float  VBa[NBATCH*UNITS];  // v ping  [b][u]
__device__ float  VBb[NBATCH*UNITS];  // v pong  [b][u]
__device__ float  CGc_[UNITS];        // cm + gleak + sum_i Wh   (recurrent)
__device__ float  CNc_[UNITS];        // gleak*vleak + sum_i WEh (recurrent)
__device__ float  SWs_[UNITS];        // sum_i Wh   (sensory)
__device__ float  SWEs_[UNITS];       // sum_i WEh  (sensory)

// sigmoid(sigma*(v-mu)) = 0.5 + 0.5*tanh(0.5*sigma*v - 0.5*sigma*mu)
// act = W*sigmoid = Wh*tanh(u) + Wh with Wh = 0.5*W; constant "+Wh" halves are
// folded into per-j column sums applied once in the combine epilogue.

__global__ __launch_bounds__(256) void prep_all(
        const float* __restrict__ rmu, const float* __restrict__ rsg,
        const float* __restrict__ rW,  const float* __restrict__ rer,
        const float* __restrict__ smu, const float* __restrict__ ssg,
        const float* __restrict__ sW,  const float* __restrict__ ser) {
    int idx = blockIdx.x*blockDim.x + threadIdx.x;
    if (idx < UNITS*UNITS) {
        float s = rsg[idx], m = rmu[idx], w = rW[idx], e = rer[idx];
        RPd[idx] = make_float4(0.5f*s, -0.5f*s*m, 0.5f*w, 0.5f*w*e);
    }
    if (idx < NIN*UNITS) {
        float s = ssg[idx], m = smu[idx], w = sW[idx], e = ser[idx];
        SPd[idx] = make_float4(0.5f*s, -0.5f*s*m, 0.5f*w, 0.5f*w*e);
    }
}

// coalesced column sums: lane = j, 8 i-rows per warp-row, smem reduce
__global__ __launch_bounds__(256) void colsums(const float* __restrict__ cm,
                                               const float* __restrict__ gl,
                                               const float* __restrict__ vl) {
    __shared__ float sm[8][32][4];
    int tx = threadIdx.x & 31;
    int ty = threadIdx.x >> 5;
    int j  = blockIdx.x*32 + tx;

    float rw = 0.f, rwe = 0.f, sw = 0.f, swe = 0.f;
    for (int i = ty; i < UNITS; i += 8) { float4 p = RPd[i*UNITS + j]; rw += p.z; rwe += p.w; }
    for (int i = ty; i < NIN;   i += 8) { float4 p = SPd[i*UNITS + j]; sw += p.z; swe += p.w; }
    sm[ty][tx][0] = rw; sm[ty][tx][1] = rwe; sm[ty][tx][2] = sw; sm[ty][tx][3] = swe;
    __syncthreads();
    if (ty == 0) {
        for (int r = 1; r < 8; r++) {
            rw += sm[r][tx][0]; rwe += sm[r][tx][1];
            sw += sm[r][tx][2]; swe += sm[r][tx][3];
        }
        SWs_[j]  = sw;
        SWEs_[j] = swe;
        CGc_[j]  = cm[j] + gl[j] + rw;
        CNc_[j]  = gl[j]*vl[j] + rwe;
    }
}

__device__ __forceinline__ float tanh_apx(float x) {
    float y;
    asm("tanh.approx.f32 %0, %1;" : "=f"(y) : "f"(x));
    return y;
}

__device__ __forceinline__ void cp_async16(uint32_t dst, const float4* src) {
    asm volatile("cp.async.cg.shared.global [%0], [%1], 16;" :: "r"(dst), "l"(src));
}
__device__ __forceinline__ void cp_commit() {
    asm volatile("cp.async.commit_group;");
}
__device__ __forceinline__ void cp_wait1() {
    asm volatile("cp.async.wait_group 1;");
}
__device__ __forceinline__ void cp_wait0() {
    asm volatile("cp.async.wait_group 0;");
}

// stage one param chunk (PCH x 32 float4 = 8 KB) into smem via cp.async
__device__ __forceinline__ void stage_params(uint32_t pbase, int buf,
                                             const float4* __restrict__ src0,
                                             int t) {
    #pragma unroll
    for (int r = 0; r < 4; r++) {
        int e = t + 128*r;           // 0..511
        int k = e >> 5;              // i within chunk
        int l = e & 31;              // j lane
        cp_async16(pbase + (uint32_t)(buf*(PCH*JT) + e)*16,
                   src0 + (size_t)k*UNITS + l);
    }
}

// ---------------- sensory partials (i-half per blockIdx.z) --------------------
__global__ __launch_bounds__(NTHR) void sensory_k(const float* __restrict__ inp,
                                                  const float* __restrict__ iw,
                                                  const float* __restrict__ ib) {
    __shared__ float  xs[(NIN/2)*VSTR];       // 10 KB
    __shared__ float4 pbuf[2][PCH*JT];        // 16 KB
    const int IH = NIN/2;                     // 128
    const int NCH = IH/PCH;                   // 8 chunks
    int jbase = blockIdx.x * JT;
    int bbase = blockIdx.y * BT;
    int ih    = blockIdx.z;
    int t = threadIdx.x;

    uint32_t pbase = (uint32_t)__cvta_generic_to_shared(pbuf);
    const float4* __restrict__ rpb = SPd + (size_t)ih*IH*UNITS + jbase;

    // prologue: stage chunk 0
    stage_params(pbase, 0, rpb, t);
    cp_commit();

    // stage x = inputs*input_w + input_b, transposed: xs[il*VSTR + b]
    for (int idx = t; idx < BT*IH; idx += NTHR) {
        int b  = idx >> 7;               // IH = 128
        int il = idx & (IH-1);
        int i  = ih*IH + il;
        xs[il*VSTR + b] = fmaf(inp[(bbase + b)*NIN + i], iw[i], ib[i]);
    }

    int tx = t & 31;
    int bg = t >> 5;                     // warp-uniform
    int j  = jbase + tx;

    float num0=0.f,num1=0.f,num2=0.f,num3=0.f;
    float den0=0.f,den1=0.f,den2=0.f,den3=0.f;

    #pragma unroll 1
    for (int c = 0; c < NCH; c++) {
        if (c + 1 < NCH) {
            stage_params(pbase, (c+1)&1, rpb + (size_t)(c+1)*PCH*UNITS, t);
            cp_commit();
            cp_wait1();
        } else {
            cp_wait0();
        }
        __syncthreads();
        const float4* pc = pbuf[c&1];
        #pragma unroll
        for (int k = 0; k < PCH; k++) {
            float4 p  = pc[k*JT + tx];
            float4 vv = *reinterpret_cast<const float4*>(xs + (c*PCH + k)*VSTR + bg*NB);
            float h0 = tanh_apx(fmaf(p.x, vv.x, p.y));
            float h1 = tanh_apx(fmaf(p.x, vv.y, p.y));
            float h2 = tanh_apx(fmaf(p.x, vv.z, p.y));
            float h3 = tanh_apx(fmaf(p.x, vv.w, p.y));
            den0 = fmaf(p.z, h0, den0); num0 = fmaf(p.w, h0, num0);
            den1 = fmaf(p.z, h1, den1); num1 = fmaf(p.w, h1, num1);
            den2 = fmaf(p.z, h2, den2); num2 = fmaf(p.w, h2, num2);
            den3 = fmaf(p.z, h3, den3); num3 = fmaf(p.w, h3, num3);
        }
        __syncthreads();
    }

    float2* __restrict__ pp = (ih == 0) ? QP0 : QP1;
    float nn[NB] = {num0,num1,num2,num3};
    float dd[NB] = {den0,den1,den2,den3};
    #pragma unroll
    for (int k = 0; k < NB; k++) {
        int b = bbase + bg*NB + k;
        pp[b*UNITS + j] = make_float2(nn[k], dd[k]);
    }
}

// combine sensory partials -> NSd/DSd (with column-sum constants folded in)
__global__ __launch_bounds__(256) void scombine_k() {
    int t = blockIdx.x*blockDim.x + threadIdx.x;   // one float4-group of j per thread
    int j4 = t & (UNITS/4 - 1);
    float4 p0a = reinterpret_cast<const float4*>(QP0)[t*2];
    float4 p0b = reinterpret_cast<const float4*>(QP0)[t*2 + 1];
    float4 p1a = reinterpret_cast<const float4*>(QP1)[t*2];
    float4 p1b = reinterpret_cast<const float4*>(QP1)[t*2 + 1];
    float4 swe = reinterpret_cast<const float4*>(SWEs_)[j4];
    float4 sw  = reinterpret_cast<const float4*>(SWs_)[j4];
    float4 ns, ds;
    ns.x = p0a.x + p1a.x + swe.x;  ds.x = p0a.y + p1a.y + sw.x;
    ns.y = p0a.z + p1a.z + swe.y;  ds.y = p0a.w + p1a.w + sw.y;
    ns.z = p0b.x + p1b.x + swe.z;  ds.z = p0b.y + p1b.y + sw.z;
    ns.w = p0b.z + p1b.z + swe.w;  ds.w = p0b.w + p1b.w + sw.w;
    reinterpret_cast<float4*>(NSd)[t] = ns;
    reinterpret_cast<float4*>(DSd)[t] = ds;
}

// ---------------- unfold partials (i-half per blockIdx.z) ---------------------
__global__ __launch_bounds__(NTHR) void unfold_k(const float* __restrict__ vext,
                                                 int in_sel) {
    __shared__ float  vs[(UNITS/2)*VSTR];     // 20 KB
    __shared__ float4 pbuf[2][PCH*JT];        // 16 KB
    const int IH = UNITS/2;                   // 256
    const int NCH = IH/PCH;                   // 16 chunks
    const float* vin = (in_sel == 0) ? vext : (in_sel == 1 ? VBa : VBb);

    int jbase = blockIdx.x * JT;
    int bbase = blockIdx.y * BT;
    int ih    = blockIdx.z;
    int t = threadIdx.x;

    uint32_t pbase = (uint32_t)__cvta_generic_to_shared(pbuf);
    const float4* __restrict__ rpb = RPd + (size_t)ih*IH*UNITS + jbase;

    // prologue: stage chunk 0
    stage_params(pbase, 0, rpb, t);
    cp_commit();

    // stage v transposed: vs[il*VSTR + b]
    for (int idx = t; idx < BT*IH; idx += NTHR) {
        int b  = idx >> 8;                // IH = 256
        int il = idx & (IH-1);
        vs[il*VSTR + b] = vin[(bbase + b)*UNITS + ih*IH + il];
    }

    int tx = t & 31;
    int bg = t >> 5;
    int j  = jbase + tx;

    float num0=0.f,num1=0.f,num2=0.f,num3=0.f;
    float den0=0.f,den1=0.f,den2=0.f,den3=0.f;

    #pragma unroll 1
    for (int c = 0; c < NCH; c++) {
        if (c + 1 < NCH) {
            stage_params(pbase, (c+1)&1, rpb + (size_t)(c+1)*PCH*UNITS, t);
            cp_commit();
            cp_wait1();
        } else {
            cp_wait0();
        }
        __syncthreads();
        const float4* pc = pbuf[c&1];
        #pragma unroll
        for (int k = 0; k < PCH; k++) {
            float4 p  = pc[k*JT + tx];
            float4 vv = *reinterpret_cast<const float4*>(vs + (c*PCH + k)*VSTR + bg*NB);
            float h0 = tanh_apx(fmaf(p.x, vv.x, p.y));
            float h1 = tanh_apx(fmaf(p.x, vv.y, p.y));
            float h2 = tanh_apx(fmaf(p.x, vv.z, p.y));
            float h3 = tanh_apx(fmaf(p.x, vv.w, p.y));
            den0 = fmaf(p.z, h0, den0); num0 = fmaf(p.w, h0, num0);
            den1 = fmaf(p.z, h1, den1); num1 = fmaf(p.w, h1, num1);
            den2 = fmaf(p.z, h2, den2); num2 = fmaf(p.w, h2, num2);
            den3 = fmaf(p.z, h3, den3); num3 = fmaf(p.w, h3, num3);
        }
        __syncthreads();
    }

    float2* __restrict__ pp = (ih == 0) ? QP0 : QP1;
    float nn[NB] = {num0,num1,num2,num3};
    float dd[NB] = {den0,den1,den2,den3};
    #pragma unroll
    for (int k = 0; k < NB; k++) {
        int b = bbase + bg*NB + k;
        pp[b*UNITS + j] = make_float2(nn[k], dd[k]);
    }
}

// combine: v' = (cm*v + CN + NS + num) / (CG + DS + den), element-wise [b][j]
__global__ __launch_bounds__(256) void combine_k(const float* __restrict__ vext,
                                                 const float* __restrict__ cm,
                                                 float* __restrict__ dout,
                                                 int in_sel, int out_sel) {
    const float* vin  = (in_sel  == 0) ? vext : (in_sel  == 1 ? VBa : VBb);
    float*       vout = (out_sel == 0) ? dout : (out_sel == 1 ? VBa : VBb);

    int t = blockIdx.x*blockDim.x + threadIdx.x;   // one float4-group of j
    int j4 = t & (UNITS/4 - 1);
    float4 vp  = reinterpret_cast<const float4*>(vin)[t];
    float4 p0a = reinterpret_cast<const float4*>(QP0)[t*2];
    float4 p0b = reinterpret_cast<const float4*>(QP0)[t*2 + 1];
    float4 p1a = reinterpret_cast<const float4*>(QP1)[t*2];
    float4 p1b = reinterpret_cast<const float4*>(QP1)[t*2 + 1];
    float4 ns  = reinterpret_cast<const float4*>(NSd)[t];
    float4 ds  = reinterpret_cast<const float4*>(DSd)[t];
    float4 cg  = reinterpret_cast<const float4*>(CGc_)[j4];
    float4 cn  = reinterpret_cast<const float4*>(CNc_)[j4];
    float4 cmv = reinterpret_cast<const float4*>(cm)[j4];

    float4 r;
    r.x = __fdividef(fmaf(cmv.x, vp.x, cn.x + ns.x + p0a.x + p1a.x),
                     cg.x + ds.x + p0a.y + p1a.y);
    r.y = __fdividef(fmaf(cmv.y, vp.y, cn.y + ns.y + p0a.z + p1a.z),
                     cg.y + ds.y + p0a.w + p1a.w);
    r.z = __fdividef(fmaf(cmv.z, vp.z, cn.z + ns.z + p0b.x + p1b.x),
                     cg.z + ds.z + p0b.y + p1b.y);
    r.w = __fdividef(fmaf(cmv.w, vp.w, cn.w + ns.w + p0b.z + p1b.z),
                     cg.w + ds.w + p0b.w + p1b.w);
    reinterpret_cast<float4*>(vout)[t] = r;
}

// ---------------- launch ------------------------------------------------------
extern "C" void kernel_launch(void* const* d_in, const int* in_sizes, int n_in,
                              void* d_out, int out_size) {
    const float* inputs = (const float*)d_in[0];
    const float* state  = (const float*)d_in[1];
    const float* iw     = (const float*)d_in[2];
    const float* ib     = (const float*)d_in[3];
    const float* smu    = (const float*)d_in[4];
    const float* ssig   = (const float*)d_in[5];
    const float* sW     = (const float*)d_in[6];
    const float* serev  = (const float*)d_in[7];
    const float* rmu    = (const float*)d_in[8];
    const float* rsig   = (const float*)d_in[9];
    const float* rW     = (const float*)d_in[10];
    const float* rerev  = (const float*)d_in[11];
    const float* vleak  = (const float*)d_in[12];
    const float* gleak  = (const float*)d_in[13];
    const float* cm     = (const float*)d_in[14];
    float* out = (float*)d_out;

    prep_all<<<(UNITS*UNITS + 255)/256, 256>>>(rmu, rsig, rW, rerev,
                                               smu, ssig, sW, serev);
    colsums<<<UNITS/32, 256>>>(cm, gleak, vleak);

    dim3 grid(UNITS/JT, NBATCH/BT, 2);     // 16 x 32 x 2 = 1024 CTAs
    const int CGRID = NBATCH*UNITS/4/256;  // 256 CTAs for combines

    sensory_k<<<grid, NTHR>>>(inputs, iw, ib);
    scombine_k<<<CGRID, 256>>>();

    // 6 unfolds: state -> VBa -> VBb -> VBa -> VBb -> VBa -> d_out
    unfold_k<<<grid, NTHR>>>(state, 0);
    combine_k<<<CGRID, 256>>>(state, cm, nullptr, 0, 1);
    unfold_k<<<grid, NTHR>>>(nullptr, 1);
    combine_k<<<CGRID, 256>>>(nullptr, cm, nullptr, 1, 2);
    unfold_k<<<grid, NTHR>>>(nullptr, 2);
    combine_k<<<CGRID, 256>>>(nullptr, cm, nullptr, 2, 1);
    unfold_k<<<grid, NTHR>>>(nullptr, 1);
    combine_k<<<CGRID, 256>>>(nullptr, cm, nullptr, 1, 2);
    unfold_k<<<grid, NTHR>>>(nullptr, 2);
    combine_k<<<CGRID, 256>>>(nullptr, cm, nullptr, 2, 1);
    unfold_k<<<grid, NTHR>>>(nullptr, 1);
    combine_k<<<CGRID, 256>>>(nullptr, cm, out, 1, 0);
}